// round 8
// baseline (speedup 1.0000x reference)
#include <cuda_runtime.h>
#include <cuda_bf16.h>
#include <cstdint>

// ---------------- problem constants ----------------
#define BB     128
#define CC     4
#define LL     10000
#define KK     20
#define NN     128
#define POUT   9980            // ceil((L-K)/stride), stride=1
#define TP     10016           // padded pair-row count (t in [0, 9998], zero-padded)
#define TILE_M 128
#define NTILE_P 78             // ceil(9980/128)
#define NUNITS (BB * NTILE_P * 2)  // 19968 work units (p-tile x n-half)
#define KSTEPS 20              // 320 / 16
#define GRID   528             // 4 CTAs/SM x 132 SMs (B300 occ4 placement cap) -> single wave

// ---------------- device scratch (static, no runtime alloc) ----------------
__device__ uint4 g_pb4[(size_t)BB * TP * 2];   // pair bf16 [b][t][16], 2 x uint4 per row
__device__ uint4 g_wb4[NN * 40];               // W bf16 [n][320], 40 x uint4 per n-row

// ---------------- smem layout (dynamic) ----------------
#define STAGE_ROWS  148
#define STAGE_PITCH 48
#define STAGE_BYTES (STAGE_ROWS * STAGE_PITCH)     // 7104
#define SMEM_STAGE  0                              // [2][7104]
#define SMEM_W      (2 * STAGE_BYTES)              // 14208
#define WPITCH      656                            // 328 bf16 per n-row (8-elem pad)
#define SMEM_TOTAL  (SMEM_W + 64 * WPITCH)         // 56192 (x4 CTAs = 224768 <= 228KB)

// ---------------- helpers ----------------
__device__ __forceinline__ uint32_t smem_u32(const void* p) {
    uint32_t a;
    asm("{ .reg .u64 t; cvta.to.shared.u64 t, %1; cvt.u32.u64 %0, t; }" : "=r"(a) : "l"(p));
    return a;
}
__device__ __forceinline__ void ldmatrix_x4(uint32_t* r, uint32_t addr) {
    asm volatile("ldmatrix.sync.aligned.m8n8.x4.shared.b16 {%0,%1,%2,%3}, [%4];"
                 : "=r"(r[0]), "=r"(r[1]), "=r"(r[2]), "=r"(r[3]) : "r"(addr));
}
__device__ __forceinline__ void mma_bf16(float* c, const uint32_t* a, const uint32_t* b) {
    asm volatile(
        "mma.sync.aligned.m16n8k16.row.col.f32.bf16.bf16.f32 "
        "{%0,%1,%2,%3}, {%4,%5,%6,%7}, {%8,%9}, {%0,%1,%2,%3};"
        : "+f"(c[0]), "+f"(c[1]), "+f"(c[2]), "+f"(c[3])
        : "r"(a[0]), "r"(a[1]), "r"(a[2]), "r"(a[3]), "r"(b[0]), "r"(b[1]));
}
__device__ __forceinline__ void cp_async16(uint32_t saddr, const void* gaddr) {
    asm volatile("cp.async.ca.shared.global [%0], [%1], 16;" :: "r"(saddr), "l"(gaddr) : "memory");
}
__device__ __forceinline__ void cp_async_commit() {
    asm volatile("cp.async.commit_group;" ::: "memory");
}
__device__ __forceinline__ void cp_async_wait0() {
    asm volatile("cp.async.wait_group 0;" ::: "memory");
}

// ---------------- merged prep kernel ----------------
__global__ void prep_all_kernel(const float* __restrict__ x, const float* __restrict__ W) {
    int gid = blockIdx.x * blockDim.x + threadIdx.x;   // gid = b*TP + t
    if (gid < BB * TP) {
        int b = gid / TP;
        int t = gid % TP;
        uint4 lo = make_uint4(0, 0, 0, 0), hi = lo;
        if (t <= LL - 2) {
            float xa[4], xb[4];
#pragma unroll
            for (int i = 0; i < 4; i++) xa[i] = x[((size_t)b * CC + i) * LL + t];
#pragma unroll
            for (int j = 0; j < 4; j++) xb[j] = x[((size_t)b * CC + j) * LL + t + 1];
            unsigned u[8];
#pragma unroll
            for (int i = 0; i < 4; i++) {
#pragma unroll
                for (int jh = 0; jh < 2; jh++) {
                    __nv_bfloat162 h = __floats2bfloat162_rn(xa[i] * xb[2 * jh], xa[i] * xb[2 * jh + 1]);
                    u[i * 2 + jh] = *reinterpret_cast<unsigned*>(&h);
                }
            }
            lo = make_uint4(u[0], u[1], u[2], u[3]);
            hi = make_uint4(u[4], u[5], u[6], u[7]);
        }
        g_pb4[(size_t)gid * 2]     = lo;
        g_pb4[(size_t)gid * 2 + 1] = hi;
    }
    if (gid < KK * CC * CC * NN) {
        int n = gid / 320;
        int rem = gid % 320;            // rem = l*16 + (i*4 + j)
        int l = rem >> 4;
        int c = rem & 15;
        int i = c >> 2, j = c & 3;
        float v = W[(((l * CC + i) * CC + j) * NN) + n];
        reinterpret_cast<__nv_bfloat16*>(g_wb4)[gid] = __float2bfloat16(v);
    }
}

// ---------------- main persistent GEMM kernel ----------------
// Work unit: 128 p-rows x 64 n-cols. 4 warps, each 32m x 64n.
// A[m][s*16+c] = stage[m+s][c]; im2col never materialized.
// nh (64-n half) constant per CTA (grid stride 528 is even).
// Single barrier per unit: iteration i's prefetch into buf^1 is ordered after
// iteration i-1's reads of buf^1 by the top-of-loop barrier.
__global__ void __launch_bounds__(128, 4) markonv_hmma_kernel(float* __restrict__ out) {
    extern __shared__ char smem[];
    const uint32_t smemS = smem_u32(smem);
    const int tid  = threadIdx.x;
    const int lane = tid & 31;
    const int wid  = tid >> 5;         // warp_m: 4 quadrants of 32 m-rows
    const int mbase = wid * 32;
    const int nh   = blockIdx.x & 1;   // constant across grid-stride iterations

    // ---- load W half-tile [64 n-rows x 320 k] once per CTA ----
    {
        int n = tid >> 1;                     // 0..63 local n-row
        int q0 = (tid & 1) * 20;
#pragma unroll
        for (int q = 0; q < 20; q++) {
            uint4 v = g_wb4[(nh * 64 + n) * 40 + q0 + q];
            *reinterpret_cast<uint4*>(smem + SMEM_W + n * WPITCH + (q0 + q) * 16) = v;
        }
    }

    // per-thread ldmatrix base addresses (invariant across tiles)
    const uint32_t aBase = smemS + SMEM_STAGE + (uint32_t)(mbase + (lane & 15)) * STAGE_PITCH
                         + (uint32_t)(lane >> 4) * 16;
    const uint32_t bBase = smemS + SMEM_W
                         + (uint32_t)((lane & 7) + ((lane >> 4) << 3)) * WPITCH
                         + (uint32_t)((lane >> 3) & 1) * 16;

    // stage-copy slots: 296 uint4 chunks (148 rows x 2) by 128 threads
    const int idx0 = tid;
    const int idx1 = tid + 128;
    const int idx2 = tid + 256;        // valid for tid < 40
    const uint32_t sD0 = smemS + SMEM_STAGE + (idx0 >> 1) * STAGE_PITCH + (idx0 & 1) * 16;
    const uint32_t sD1 = smemS + SMEM_STAGE + (idx1 >> 1) * STAGE_PITCH + (idx1 & 1) * 16;
    const uint32_t sD2 = smemS + SMEM_STAGE + (idx2 >> 1) * STAGE_PITCH + (idx2 & 1) * 16;

    auto prefetch = [&](int unit, int buf) {
        if (unit >= NUNITS) return;
        int ptile = unit >> 1;
        int b  = ptile / NTILE_P;
        int p0 = (ptile % NTILE_P) * TILE_M;
        const uint4* src = &g_pb4[((size_t)b * TP + p0) * 2];
        uint32_t bofs = (uint32_t)buf * STAGE_BYTES;
        cp_async16(sD0 + bofs, src + idx0);
        cp_async16(sD1 + bofs, src + idx1);
        if (idx2 < 2 * STAGE_ROWS) cp_async16(sD2 + bofs, src + idx2);
        cp_async_commit();
    };

    int unit = blockIdx.x;
    prefetch(unit, 0);
    int buf = 0;

    for (; unit < NUNITS; unit += GRID, buf ^= 1) {
        cp_async_wait0();
        __syncthreads();                       // buf staged AND all prior reads of buf^1 done
        prefetch(unit + GRID, buf ^ 1);

        int ptile = unit >> 1;
        int b  = ptile / NTILE_P;
        int p0 = (ptile % NTILE_P) * TILE_M;
        const uint32_t aB = aBase + (uint32_t)buf * STAGE_BYTES;

        float c[2][8][4];
#pragma unroll
        for (int mf = 0; mf < 2; mf++)
#pragma unroll
            for (int nf = 0; nf < 8; nf++)
#pragma unroll
                for (int r = 0; r < 4; r++) c[mf][nf][r] = 0.0f;

#pragma unroll
        for (int s = 0; s < KSTEPS; s++) {
            uint32_t a[2][4];
#pragma unroll
            for (int mf = 0; mf < 2; mf++)
                ldmatrix_x4(a[mf], aB + (uint32_t)s * STAGE_PITCH + (uint32_t)mf * (16 * STAGE_PITCH));

            uint32_t bb[8][2];
#pragma unroll
            for (int nb = 0; nb < 4; nb++) {
                uint32_t r4[4];
                ldmatrix_x4(r4, bBase + (uint32_t)s * 32 + (uint32_t)nb * (16 * WPITCH));
                bb[2 * nb][0]     = r4[0];
                bb[2 * nb][1]     = r4[1];
                bb[2 * nb + 1][0] = r4[2];
                bb[2 * nb + 1][1] = r4[3];
            }

#pragma unroll
            for (int mf = 0; mf < 2; mf++)
#pragma unroll
                for (int nf = 0; nf < 8; nf++)
                    mma_bf16(c[mf][nf], a[mf], bb[nf]);
        }

        // ---- epilogue: c(row p', col n_local) -> out[b][nh*64 + n][p0 + p'] ----
        float* outb = out + (size_t)b * NN * POUT + (size_t)(nh * 64) * POUT;
        int pq = p0 + mbase + (lane >> 2);
        int nc = (lane & 3) * 2;
#pragma unroll
        for (int mf = 0; mf < 2; mf++) {
#pragma unroll
            for (int half = 0; half < 2; half++) {
                int p = pq + mf * 16 + half * 8;
                if (p < POUT) {
#pragma unroll
                    for (int nf = 0; nf < 8; nf++) {
                        int n = nc + nf * 8;
                        outb[(size_t)n * POUT + p]       = c[mf][nf][half * 2];
                        outb[(size_t)(n + 1) * POUT + p] = c[mf][nf][half * 2 + 1];
                    }
                }
            }
        }
        // no end-of-loop barrier needed: next iteration's top barrier orders
        // the next prefetch-write of this buffer after all reads above.
    }
}

// ---------------- launch ----------------
extern "C" void kernel_launch(void* const* d_in, const int* in_sizes, int n_in,
                              void* d_out, int out_size) {
    const float* x = (const float*)d_in[0];
    const float* W = (const float*)d_in[1];
    if (n_in >= 2 && in_sizes[0] == KK * CC * CC * NN && in_sizes[1] == BB * CC * LL) {
        const float* t = x; x = W; W = t;   // defensive: swapped order
    }
    float* out = (float*)d_out;

    prep_all_kernel<<<(BB * TP + 127) / 128, 128>>>(x, W);

    cudaFuncSetAttribute(markonv_hmma_kernel, cudaFuncAttributeMaxDynamicSharedMemorySize, SMEM_TOTAL);
    markonv_hmma_kernel<<<GRID, 128, SMEM_TOTAL>>>(out);
}

// round 9
// speedup vs baseline: 1.0987x; 1.0987x over previous
#include <cuda_runtime.h>
#include <cuda_bf16.h>
#include <cstdint>

// ---------------- problem constants ----------------
#define BB     128
#define CC     4
#define LL     10000
#define KK     20
#define NN     128
#define POUT   9980            // ceil((L-K)/stride), stride=1
#define TP     10016           // padded pair-row count (t in [0, 9998], zero-padded)
#define TILE_M 128
#define NTILE_P 78             // ceil(9980/128)
#define NUNITS (BB * NTILE_P * 2)  // 19968 work units (p-tile x n-half)
#define KSTEPS 20              // 320 / 16
#define GRID   592             // 4 CTAs/SM x 148 SMs, single balanced wave (R6 winner config)

// ---------------- device scratch (static, no runtime alloc) ----------------
__device__ uint4 g_pb4[(size_t)BB * TP * 2];   // pair bf16 [b][t][16], 2 x uint4 per row
__device__ uint4 g_wb4[NN * 40];               // W bf16 [n][320], 40 x uint4 per n-row

// ---------------- smem layout (dynamic) ----------------
#define STAGE_ROWS  148
#define STAGE_PITCH 48
#define STAGE_BYTES (STAGE_ROWS * STAGE_PITCH)     // 7104
#define SMEM_STAGE  0                              // [2][7104]
#define SMEM_W      (2 * STAGE_BYTES)              // 14208
#define WPITCH      656                            // 328 bf16 per n-row (8-elem pad)
#define SMEM_TOTAL  (SMEM_W + 64 * WPITCH)         // 56192 (x4 CTAs = 224768 <= 228KB)

// ---------------- helpers ----------------
__device__ __forceinline__ uint32_t smem_u32(const void* p) {
    uint32_t a;
    asm("{ .reg .u64 t; cvta.to.shared.u64 t, %1; cvt.u32.u64 %0, t; }" : "=r"(a) : "l"(p));
    return a;
}
__device__ __forceinline__ void ldmatrix_x4(uint32_t* r, uint32_t addr) {
    asm volatile("ldmatrix.sync.aligned.m8n8.x4.shared.b16 {%0,%1,%2,%3}, [%4];"
                 : "=r"(r[0]), "=r"(r[1]), "=r"(r[2]), "=r"(r[3]) : "r"(addr));
}
__device__ __forceinline__ void mma_bf16(float* c, const uint32_t* a, const uint32_t* b) {
    asm volatile(
        "mma.sync.aligned.m16n8k16.row.col.f32.bf16.bf16.f32 "
        "{%0,%1,%2,%3}, {%4,%5,%6,%7}, {%8,%9}, {%0,%1,%2,%3};"
        : "+f"(c[0]), "+f"(c[1]), "+f"(c[2]), "+f"(c[3])
        : "r"(a[0]), "r"(a[1]), "r"(a[2]), "r"(a[3]), "r"(b[0]), "r"(b[1]));
}
__device__ __forceinline__ void cp_async16(uint32_t saddr, const void* gaddr) {
    asm volatile("cp.async.ca.shared.global [%0], [%1], 16;" :: "r"(saddr), "l"(gaddr) : "memory");
}
__device__ __forceinline__ void cp_async_commit() {
    asm volatile("cp.async.commit_group;" ::: "memory");
}
__device__ __forceinline__ void cp_async_wait0() {
    asm volatile("cp.async.wait_group 0;" ::: "memory");
}

// ---------------- merged prep kernel ----------------
__global__ void prep_all_kernel(const float* __restrict__ x, const float* __restrict__ W) {
    int gid = blockIdx.x * blockDim.x + threadIdx.x;   // gid = b*TP + t
    if (gid < BB * TP) {
        int b = gid / TP;
        int t = gid % TP;
        uint4 lo = make_uint4(0, 0, 0, 0), hi = lo;
        if (t <= LL - 2) {
            float xa[4], xb[4];
#pragma unroll
            for (int i = 0; i < 4; i++) xa[i] = x[((size_t)b * CC + i) * LL + t];
#pragma unroll
            for (int j = 0; j < 4; j++) xb[j] = x[((size_t)b * CC + j) * LL + t + 1];
            unsigned u[8];
#pragma unroll
            for (int i = 0; i < 4; i++) {
#pragma unroll
                for (int jh = 0; jh < 2; jh++) {
                    __nv_bfloat162 h = __floats2bfloat162_rn(xa[i] * xb[2 * jh], xa[i] * xb[2 * jh + 1]);
                    u[i * 2 + jh] = *reinterpret_cast<unsigned*>(&h);
                }
            }
            lo = make_uint4(u[0], u[1], u[2], u[3]);
            hi = make_uint4(u[4], u[5], u[6], u[7]);
        }
        g_pb4[(size_t)gid * 2]     = lo;
        g_pb4[(size_t)gid * 2 + 1] = hi;
    }
    if (gid < KK * CC * CC * NN) {
        int n = gid / 320;
        int rem = gid % 320;            // rem = l*16 + (i*4 + j)
        int l = rem >> 4;
        int c = rem & 15;
        int i = c >> 2, j = c & 3;
        float v = W[(((l * CC + i) * CC + j) * NN) + n];
        reinterpret_cast<__nv_bfloat16*>(g_wb4)[gid] = __float2bfloat16(v);
    }
}

// ---------------- main persistent GEMM kernel ----------------
// Work unit: 128 p-rows x 64 n-cols. 4 warps, each 32m x 64n.
// A[m][s*16+c] = stage[m+s][c]; im2col never materialized.
// nh (64-n half) constant per CTA (grid stride 592 is even).
__global__ void __launch_bounds__(128, 4) markonv_hmma_kernel(float* __restrict__ out) {
    extern __shared__ char smem[];
    const uint32_t smemS = smem_u32(smem);
    const int tid  = threadIdx.x;
    const int lane = tid & 31;
    const int wid  = tid >> 5;         // warp_m: 4 quadrants of 32 m-rows
    const int mbase = wid * 32;
    const int nh   = blockIdx.x & 1;   // constant across grid-stride iterations

    // ---- load W half-tile [64 n-rows x 320 k] once per CTA ----
    {
        int n = tid >> 1;                     // 0..63 local n-row
        int q0 = (tid & 1) * 20;
#pragma unroll
        for (int q = 0; q < 20; q++) {
            uint4 v = g_wb4[(nh * 64 + n) * 40 + q0 + q];
            *reinterpret_cast<uint4*>(smem + SMEM_W + n * WPITCH + (q0 + q) * 16) = v;
        }
    }

    // per-thread ldmatrix base addresses (invariant across tiles)
    const uint32_t aBase = smemS + SMEM_STAGE + (uint32_t)(mbase + (lane & 15)) * STAGE_PITCH
                         + (uint32_t)(lane >> 4) * 16;
    const uint32_t bBase = smemS + SMEM_W
                         + (uint32_t)((lane & 7) + ((lane >> 4) << 3)) * WPITCH
                         + (uint32_t)((lane >> 3) & 1) * 16;

    // stage-copy slots: 296 uint4 chunks (148 rows x 2) by 128 threads
    const int idx0 = tid;
    const int idx1 = tid + 128;
    const int idx2 = tid + 256;        // valid for tid < 40
    const uint32_t sD0 = smemS + SMEM_STAGE + (idx0 >> 1) * STAGE_PITCH + (idx0 & 1) * 16;
    const uint32_t sD1 = smemS + SMEM_STAGE + (idx1 >> 1) * STAGE_PITCH + (idx1 & 1) * 16;
    const uint32_t sD2 = smemS + SMEM_STAGE + (idx2 >> 1) * STAGE_PITCH + (idx2 & 1) * 16;

    auto prefetch = [&](int unit, int buf) {
        if (unit >= NUNITS) return;
        int ptile = unit >> 1;
        int b  = ptile / NTILE_P;
        int p0 = (ptile % NTILE_P) * TILE_M;
        const uint4* src = &g_pb4[((size_t)b * TP + p0) * 2];
        uint32_t bofs = (uint32_t)buf * STAGE_BYTES;
        cp_async16(sD0 + bofs, src + idx0);
        cp_async16(sD1 + bofs, src + idx1);
        if (idx2 < 2 * STAGE_ROWS) cp_async16(sD2 + bofs, src + idx2);
        cp_async_commit();
    };

    int unit = blockIdx.x;
    prefetch(unit, 0);
    int buf = 0;

    for (; unit < NUNITS; unit += GRID, buf ^= 1) {
        cp_async_wait0();
        __syncthreads();
        prefetch(unit + GRID, buf ^ 1);

        int ptile = unit >> 1;
        int b  = ptile / NTILE_P;
        int p0 = (ptile % NTILE_P) * TILE_M;
        const uint32_t aB = aBase + (uint32_t)buf * STAGE_BYTES;

        float c[2][8][4];
#pragma unroll
        for (int mf = 0; mf < 2; mf++)
#pragma unroll
            for (int nf = 0; nf < 8; nf++)
#pragma unroll
                for (int r = 0; r < 4; r++) c[mf][nf][r] = 0.0f;

#pragma unroll
        for (int s = 0; s < KSTEPS; s++) {
            uint32_t a[2][4];
#pragma unroll
            for (int mf = 0; mf < 2; mf++)
                ldmatrix_x4(a[mf], aB + (uint32_t)s * STAGE_PITCH + (uint32_t)mf * (16 * STAGE_PITCH));

            uint32_t bb[8][2];
#pragma unroll
            for (int nb = 0; nb < 4; nb++) {
                uint32_t r4[4];
                ldmatrix_x4(r4, bBase + (uint32_t)s * 32 + (uint32_t)nb * (16 * WPITCH));
                bb[2 * nb][0]     = r4[0];
                bb[2 * nb][1]     = r4[1];
                bb[2 * nb + 1][0] = r4[2];
                bb[2 * nb + 1][1] = r4[3];
            }

#pragma unroll
            for (int mf = 0; mf < 2; mf++)
#pragma unroll
                for (int nf = 0; nf < 8; nf++)
                    mma_bf16(c[mf][nf], a[mf], bb[nf]);
        }

        // ---- epilogue: c(row p', col n_local) -> out[b][nh*64 + n][p0 + p'] ----
        // Streaming (evict-first) stores: the 654MB output stream must not evict
        // the pair-stage / W lines that cp.async re-reads from L2.
        float* outb = out + (size_t)b * NN * POUT + (size_t)(nh * 64) * POUT;
        int pq = p0 + mbase + (lane >> 2);
        int nc = (lane & 3) * 2;
#pragma unroll
        for (int mf = 0; mf < 2; mf++) {
#pragma unroll
            for (int half = 0; half < 2; half++) {
                int p = pq + mf * 16 + half * 8;
                if (p < POUT) {
#pragma unroll
                    for (int nf = 0; nf < 8; nf++) {
                        int n = nc + nf * 8;
                        __stcs(&outb[(size_t)n * POUT + p],       c[mf][nf][half * 2]);
                        __stcs(&outb[(size_t)(n + 1) * POUT + p], c[mf][nf][half * 2 + 1]);
                    }
                }
            }
        }
        __syncthreads();   // all reads of `buf` done before refill (2 units ahead)
    }
}

// ---------------- launch ----------------
extern "C" void kernel_launch(void* const* d_in, const int* in_sizes, int n_in,
                              void* d_out, int out_size) {
    const float* x = (const float*)d_in[0];
    const float* W = (const float*)d_in[1];
    if (n_in >= 2 && in_sizes[0] == KK * CC * CC * NN && in_sizes[1] == BB * CC * LL) {
        const float* t = x; x = W; W = t;   // defensive: swapped order
    }
    float* out = (float*)d_out;

    prep_all_kernel<<<(BB * TP + 127) / 128, 128>>>(x, W);

    cudaFuncSetAttribute(markonv_hmma_kernel, cudaFuncAttributeMaxDynamicSharedMemorySize, SMEM_TOTAL);
    markonv_hmma_kernel<<<GRID, 128, SMEM_TOTAL>>>(out);
}

// round 10
// speedup vs baseline: 1.7878x; 1.6272x over previous
#include <cuda_runtime.h>
#include <cuda_bf16.h>
#include <cstdint>

// ---------------- problem constants ----------------
#define BB     128
#define CC     4
#define LL     10000
#define KK     20
#define NN     128
#define POUT   9980            // ceil((L-K)/stride), stride=1
#define TP     10016           // padded pair-row count (t in [0, 9998], zero-padded)
#define TILE_M 128
#define NTILE_P 78             // ceil(9980/128)
#define NUNITS (BB * NTILE_P * 2)  // 19968 work units (p-tile x n-half)
#define KSTEPS 20              // 320 / 16
#define GRID   444             // 3 CTAs/SM x 148 SMs = true residency (regs cap 4th CTA), single wave

// ---------------- device scratch (static, no runtime alloc) ----------------
__device__ uint4 g_pb4[(size_t)BB * TP * 2];   // pair bf16 [b][t][16], 2 x uint4 per row
__device__ uint4 g_wb4[NN * 40];               // W bf16 [n][320], 40 x uint4 per n-row

// ---------------- smem layout (dynamic) ----------------
#define STAGE_ROWS  148
#define STAGE_PITCH 48
#define STAGE_BYTES (STAGE_ROWS * STAGE_PITCH)     // 7104
#define SMEM_STAGE  0                              // [2][7104]
#define SMEM_W      (2 * STAGE_BYTES)              // 14208
#define WPITCH      656                            // 328 bf16 per n-row (8-elem pad)
#define SMEM_TOTAL  (SMEM_W + 64 * WPITCH)         // 56192 (x3 CTAs = 168576)

// ---------------- helpers ----------------
__device__ __forceinline__ uint32_t smem_u32(const void* p) {
    uint32_t a;
    asm("{ .reg .u64 t; cvta.to.shared.u64 t, %1; cvt.u32.u64 %0, t; }" : "=r"(a) : "l"(p));
    return a;
}
__device__ __forceinline__ void ldmatrix_x4(uint32_t* r, uint32_t addr) {
    asm volatile("ldmatrix.sync.aligned.m8n8.x4.shared.b16 {%0,%1,%2,%3}, [%4];"
                 : "=r"(r[0]), "=r"(r[1]), "=r"(r[2]), "=r"(r[3]) : "r"(addr));
}
__device__ __forceinline__ void mma_bf16(float* c, const uint32_t* a, const uint32_t* b) {
    asm volatile(
        "mma.sync.aligned.m16n8k16.row.col.f32.bf16.bf16.f32 "
        "{%0,%1,%2,%3}, {%4,%5,%6,%7}, {%8,%9}, {%0,%1,%2,%3};"
        : "+f"(c[0]), "+f"(c[1]), "+f"(c[2]), "+f"(c[3])
        : "r"(a[0]), "r"(a[1]), "r"(a[2]), "r"(a[3]), "r"(b[0]), "r"(b[1]));
}
__device__ __forceinline__ void cp_async16(uint32_t saddr, const void* gaddr) {
    asm volatile("cp.async.ca.shared.global [%0], [%1], 16;" :: "r"(saddr), "l"(gaddr) : "memory");
}
__device__ __forceinline__ void cp_async_commit() {
    asm volatile("cp.async.commit_group;" ::: "memory");
}
__device__ __forceinline__ void cp_async_wait0() {
    asm volatile("cp.async.wait_group 0;" ::: "memory");
}

// ---------------- merged prep kernel ----------------
__global__ void prep_all_kernel(const float* __restrict__ x, const float* __restrict__ W) {
    int gid = blockIdx.x * blockDim.x + threadIdx.x;   // gid = b*TP + t
    if (gid < BB * TP) {
        int b = gid / TP;
        int t = gid % TP;
        uint4 lo = make_uint4(0, 0, 0, 0), hi = lo;
        if (t <= LL - 2) {
            float xa[4], xb[4];
#pragma unroll
            for (int i = 0; i < 4; i++) xa[i] = x[((size_t)b * CC + i) * LL + t];
#pragma unroll
            for (int j = 0; j < 4; j++) xb[j] = x[((size_t)b * CC + j) * LL + t + 1];
            unsigned u[8];
#pragma unroll
            for (int i = 0; i < 4; i++) {
#pragma unroll
                for (int jh = 0; jh < 2; jh++) {
                    __nv_bfloat162 h = __floats2bfloat162_rn(xa[i] * xb[2 * jh], xa[i] * xb[2 * jh + 1]);
                    u[i * 2 + jh] = *reinterpret_cast<unsigned*>(&h);
                }
            }
            lo = make_uint4(u[0], u[1], u[2], u[3]);
            hi = make_uint4(u[4], u[5], u[6], u[7]);
        }
        g_pb4[(size_t)gid * 2]     = lo;
        g_pb4[(size_t)gid * 2 + 1] = hi;
    }
    if (gid < KK * CC * CC * NN) {
        int n = gid / 320;
        int rem = gid % 320;            // rem = l*16 + (i*4 + j)
        int l = rem >> 4;
        int c = rem & 15;
        int i = c >> 2, j = c & 3;
        float v = W[(((l * CC + i) * CC + j) * NN) + n];
        reinterpret_cast<__nv_bfloat16*>(g_wb4)[gid] = __float2bfloat16(v);
    }
}

// ---------------- main persistent GEMM kernel ----------------
// Work unit: 128 p-rows x 64 n-cols. 4 warps, each 32m x 64n.
// A[m][s*16+c] = stage[m+s][c]; im2col never materialized.
// nh (64-n half) constant per CTA (grid stride 444 is even).
__global__ void __launch_bounds__(128, 3) markonv_hmma_kernel(float* __restrict__ out) {
    extern __shared__ char smem[];
    const uint32_t smemS = smem_u32(smem);
    const int tid  = threadIdx.x;
    const int lane = tid & 31;
    const int wid  = tid >> 5;         // warp_m: 4 quadrants of 32 m-rows
    const int mbase = wid * 32;
    const int nh   = blockIdx.x & 1;   // constant across grid-stride iterations

    // ---- load W half-tile [64 n-rows x 320 k] once per CTA ----
    {
        int n = tid >> 1;                     // 0..63 local n-row
        int q0 = (tid & 1) * 20;
#pragma unroll
        for (int q = 0; q < 20; q++) {
            uint4 v = g_wb4[(nh * 64 + n) * 40 + q0 + q];
            *reinterpret_cast<uint4*>(smem + SMEM_W + n * WPITCH + (q0 + q) * 16) = v;
        }
    }

    // per-thread ldmatrix base addresses (invariant across tiles)
    const uint32_t aBase = smemS + SMEM_STAGE + (uint32_t)(mbase + (lane & 15)) * STAGE_PITCH
                         + (uint32_t)(lane >> 4) * 16;
    const uint32_t bBase = smemS + SMEM_W
                         + (uint32_t)((lane & 7) + ((lane >> 4) << 3)) * WPITCH
                         + (uint32_t)((lane >> 3) & 1) * 16;

    // stage-copy slots: 296 uint4 chunks (148 rows x 2) by 128 threads
    const int idx0 = tid;
    const int idx1 = tid + 128;
    const int idx2 = tid + 256;        // valid for tid < 40
    const uint32_t sD0 = smemS + SMEM_STAGE + (idx0 >> 1) * STAGE_PITCH + (idx0 & 1) * 16;
    const uint32_t sD1 = smemS + SMEM_STAGE + (idx1 >> 1) * STAGE_PITCH + (idx1 & 1) * 16;
    const uint32_t sD2 = smemS + SMEM_STAGE + (idx2 >> 1) * STAGE_PITCH + (idx2 & 1) * 16;

    auto prefetch = [&](int unit, int buf) {
        if (unit >= NUNITS) return;
        int ptile = unit >> 1;
        int b  = ptile / NTILE_P;
        int p0 = (ptile % NTILE_P) * TILE_M;
        const uint4* src = &g_pb4[((size_t)b * TP + p0) * 2];
        uint32_t bofs = (uint32_t)buf * STAGE_BYTES;
        cp_async16(sD0 + bofs, src + idx0);
        cp_async16(sD1 + bofs, src + idx1);
        if (idx2 < 2 * STAGE_ROWS) cp_async16(sD2 + bofs, src + idx2);
        cp_async_commit();
    };

    int unit = blockIdx.x;
    prefetch(unit, 0);
    int buf = 0;

    for (; unit < NUNITS; unit += GRID, buf ^= 1) {
        cp_async_wait0();
        __syncthreads();
        prefetch(unit + GRID, buf ^ 1);

        int ptile = unit >> 1;
        int b  = ptile / NTILE_P;
        int p0 = (ptile % NTILE_P) * TILE_M;
        const uint32_t aB = aBase + (uint32_t)buf * STAGE_BYTES;

        float c[2][8][4];
#pragma unroll
        for (int mf = 0; mf < 2; mf++)
#pragma unroll
            for (int nf = 0; nf < 8; nf++)
#pragma unroll
                for (int r = 0; r < 4; r++) c[mf][nf][r] = 0.0f;

#pragma unroll
        for (int s = 0; s < KSTEPS; s++) {
            uint32_t a[2][4];
#pragma unroll
            for (int mf = 0; mf < 2; mf++)
                ldmatrix_x4(a[mf], aB + (uint32_t)s * STAGE_PITCH + (uint32_t)mf * (16 * STAGE_PITCH));

            uint32_t bb[8][2];
#pragma unroll
            for (int nb = 0; nb < 4; nb++) {
                uint32_t r4[4];
                ldmatrix_x4(r4, bBase + (uint32_t)s * 32 + (uint32_t)nb * (16 * WPITCH));
                bb[2 * nb][0]     = r4[0];
                bb[2 * nb][1]     = r4[1];
                bb[2 * nb + 1][0] = r4[2];
                bb[2 * nb + 1][1] = r4[3];
            }

#pragma unroll
            for (int mf = 0; mf < 2; mf++)
#pragma unroll
                for (int nf = 0; nf < 8; nf++)
                    mma_bf16(c[mf][nf], a[mf], bb[nf]);
        }

        // ---- epilogue: c(row p', col n_local) -> out[b][nh*64 + n][p0 + p'] ----
        // Streaming (evict-first) stores keep the 654MB output stream out of L2's way.
        float* outb = out + (size_t)b * NN * POUT + (size_t)(nh * 64) * POUT;
        int pq = p0 + mbase + (lane >> 2);
        int nc = (lane & 3) * 2;
#pragma unroll
        for (int mf = 0; mf < 2; mf++) {
#pragma unroll
            for (int half = 0; half < 2; half++) {
                int p = pq + mf * 16 + half * 8;
                if (p < POUT) {
#pragma unroll
                    for (int nf = 0; nf < 8; nf++) {
                        int n = nc + nf * 8;
                        __stcs(&outb[(size_t)n * POUT + p],       c[mf][nf][half * 2]);
                        __stcs(&outb[(size_t)(n + 1) * POUT + p], c[mf][nf][half * 2 + 1]);
                    }
                }
            }
        }
        __syncthreads();   // all reads of `buf` done before refill (2 units ahead)
    }
}

// ---------------- launch ----------------
extern "C" void kernel_launch(void* const* d_in, const int* in_sizes, int n_in,
                              void* d_out, int out_size) {
    const float* x = (const float*)d_in[0];
    const float* W = (const float*)d_in[1];
    if (n_in >= 2 && in_sizes[0] == KK * CC * CC * NN && in_sizes[1] == BB * CC * LL) {
        const float* t = x; x = W; W = t;   // defensive: swapped order
    }
    float* out = (float*)d_out;

    prep_all_kernel<<<(BB * TP + 127) / 128, 128>>>(x, W);

    cudaFuncSetAttribute(markonv_hmma_kernel, cudaFuncAttributeMaxDynamicSharedMemorySize, SMEM_TOTAL);
    markonv_hmma_kernel<<<GRID, 128, SMEM_TOTAL>>>(out);
}